// round 11
// baseline (speedup 1.0000x reference)
#include <cuda_runtime.h>
#include <cuda_bf16.h>
#include <math.h>
#include <stdint.h>

// Problem constants
#define BB 4
#define SS 2048
#define DD 768
#define HH 12
#define DKK 64
#define MROWS (BB*SS)        // 8192

// Scratch (zero-init .bss; no runtime allocation)
__device__ float g_Q[BB*HH*SS*DKK];   // [B,H,S,DK]
__device__ float g_K[BB*HH*SS*DKK];
__device__ float g_V[BB*HH*SS*DKK];
__device__ float g_X[BB*SS*DD];       // attention output, [B,S,D]
__device__ uint32_t g_Wtf[4][DD*DD];  // weights pre-converted to tf32 bits
__device__ float2 g_ropecs[SS*32];    // (cos, sin) per (s, pair)

// ---------------------------------------------------------------------------
// Helpers
// ---------------------------------------------------------------------------
__device__ __forceinline__ uint32_t f2tf(float x) {
    uint32_t r;
    asm("cvt.rna.tf32.f32 %0, %1;" : "=r"(r) : "f"(x));
    return r;
}

__device__ __forceinline__ void mma_tf32(float* c, const uint32_t* a, const uint32_t* b) {
    asm volatile(
        "mma.sync.aligned.m16n8k8.row.col.f32.tf32.tf32.f32 "
        "{%0,%1,%2,%3}, {%4,%5,%6,%7}, {%8,%9}, {%0,%1,%2,%3};"
        : "+f"(c[0]), "+f"(c[1]), "+f"(c[2]), "+f"(c[3])
        : "r"(a[0]), "r"(a[1]), "r"(a[2]), "r"(a[3]), "r"(b[0]), "r"(b[1]));
}

__device__ __forceinline__ uint32_t smem_u32(const void* p) {
    uint32_t a;
    asm("{ .reg .u64 t; cvta.to.shared.u64 t, %1; cvt.u32.u64 %0, t; }"
        : "=r"(a) : "l"(p));
    return a;
}

__device__ __forceinline__ void cp16(uint32_t dst, const void* src) {
    asm volatile("cp.async.cg.shared.global [%0], [%1], 16;" :: "r"(dst), "l"(src));
}
#define CP_COMMIT() asm volatile("cp.async.commit_group;" ::: "memory")
#define CP_WAIT(N)  asm volatile("cp.async.wait_group %0;" :: "n"(N) : "memory")

// ---------------------------------------------------------------------------
// Pre-pass 1: RoPE cos/sin table. f32 angle (matches ref), double mod 2pi.
// ---------------------------------------------------------------------------
__global__ __launch_bounds__(256) void rope_table_kernel()
{
    const int t = blockIdx.x * blockDim.x + threadIdx.x;   // 2048*32
    const int i = t & 31, s = t >> 5;
    if (s >= SS) return;
    const float theta = powf(10000.f, (-2.f / 64.f) * (float)i);
    const float ang = (float)s * theta;
    const double TWO_PI = 6.283185307179586476925286766559;
    double ad = (double)ang;
    double r = ad - TWO_PI * floor(ad / TWO_PI);
    float rf = (float)r;
    g_ropecs[t] = make_float2(cosf(rf), sinf(rf));
}

// ---------------------------------------------------------------------------
// Pre-pass 2: convert 4 weight matrices to tf32 bits.
// ---------------------------------------------------------------------------
__global__ __launch_bounds__(256) void cvt_w_kernel(
    const float* __restrict__ Wq, const float* __restrict__ Wk,
    const float* __restrict__ Wv, const float* __restrict__ Wo)
{
    const float* W = (blockIdx.y == 0) ? Wq : (blockIdx.y == 1) ? Wk
                   : (blockIdx.y == 2) ? Wv : Wo;
    uint32_t* O = g_Wtf[blockIdx.y];
    const int i = (blockIdx.x * blockDim.x + threadIdx.x) * 4;
    float4 w = *(const float4*)(W + i);
    uint4 u;
    u.x = f2tf(w.x); u.y = f2tf(w.y); u.z = f2tf(w.z); u.w = f2tf(w.w);
    *(uint4*)(O + i) = u;
}

// ---------------------------------------------------------------------------
// cp.async-pipelined tf32 GEMM (unchanged from R8, passing).
// ---------------------------------------------------------------------------
#define ST_U32   8960                   // per stage: A 128*36 + B 32*136
#define GT_SMEM_BYTES (3 * ST_U32 * 4)  // 107520 B

template <int SCATTER>
__device__ __forceinline__ void gemm_pipe_body(
    const float* __restrict__ A, const uint32_t* __restrict__ Wtf,
    const float* __restrict__ bias, float* __restrict__ Out, bool dorope)
{
    extern __shared__ char smem[];
    const uint32_t sbase = smem_u32(smem);
    const int tid = threadIdx.x;
    const int lane = tid & 31, wid = tid >> 5;
    const int g = lane >> 2, t4 = lane & 3;
    const int wm = (wid & 1) * 64;
    const int wn = (wid >> 1) * 32;
    const int bm = blockIdx.y * 128, bn = blockIdx.x * 128;

    auto issue = [&](int ic, int st) {
        const int k0 = ic * 32;
        const uint32_t sb = sbase + st * (ST_U32 * 4);
#pragma unroll
        for (int it = 0; it < 4; it++) {
            const int seg = tid + it * 256;
            const int row = seg >> 3, c4 = (seg & 7) * 4;
            cp16(sb + (row * 36 + c4) * 4,
                 A + (size_t)(bm + row) * DD + k0 + c4);
        }
#pragma unroll
        for (int it = 0; it < 4; it++) {
            const int seg = tid + it * 256;
            const int row = seg >> 5, c4 = (seg & 31) * 4;
            cp16(sb + (4608 + row * 136 + c4) * 4,
                 Wtf + (size_t)(k0 + row) * DD + bn + c4);
        }
        CP_COMMIT();
    };

    float acc[4][4][4];
#pragma unroll
    for (int mi = 0; mi < 4; mi++)
#pragma unroll
        for (int ni = 0; ni < 4; ni++)
#pragma unroll
            for (int r = 0; r < 4; r++) acc[mi][ni][r] = 0.f;

    issue(0, 0);
    issue(1, 1);

    for (int ic = 0; ic < 24; ic++) {
        if (ic + 2 < 24) { issue(ic + 2, (ic + 2) % 3); CP_WAIT(2); }
        else if (ic + 1 < 24) { CP_WAIT(1); }
        else { CP_WAIT(0); }
        __syncthreads();

        const int st = ic % 3;
        const float* As = (const float*)smem + st * ST_U32;
        const uint32_t* Bs = (const uint32_t*)smem + st * ST_U32 + 4608;

#pragma unroll
        for (int k8 = 0; k8 < 4; k8++) {
            const int kb = k8 * 8;
            uint32_t af[4][4];
#pragma unroll
            for (int mi = 0; mi < 4; mi++) {
                const int r = wm + mi * 16 + g;
                af[mi][0] = f2tf(As[r * 36 + kb + t4]);
                af[mi][1] = f2tf(As[(r + 8) * 36 + kb + t4]);
                af[mi][2] = f2tf(As[r * 36 + kb + t4 + 4]);
                af[mi][3] = f2tf(As[(r + 8) * 36 + kb + t4 + 4]);
            }
            uint32_t bf[4][2];
#pragma unroll
            for (int ni = 0; ni < 4; ni++) {
                const int cn = wn + ni * 8 + g;
                bf[ni][0] = Bs[(kb + t4) * 136 + cn];
                bf[ni][1] = Bs[(kb + t4 + 4) * 136 + cn];
            }
#pragma unroll
            for (int mi = 0; mi < 4; mi++)
#pragma unroll
                for (int ni = 0; ni < 4; ni++)
                    mma_tf32(acc[mi][ni], af[mi], bf[ni]);
        }
        __syncthreads();
    }

#pragma unroll
    for (int mi = 0; mi < 4; mi++) {
#pragma unroll
        for (int ni = 0; ni < 4; ni++) {
            const int row = bm + wm + mi * 16 + g;
            const int col = bn + wn + ni * 8 + 2 * t4;
            const float b0 = bias[col], b1 = bias[col + 1];
            float2 v0 = make_float2(acc[mi][ni][0] + b0, acc[mi][ni][1] + b1);
            float2 v1 = make_float2(acc[mi][ni][2] + b0, acc[mi][ni][3] + b1);
            const int s = row & (SS - 1);
            if (dorope) {
                const int pi = (col & 63) >> 1;
                const float2 cs0 = g_ropecs[s * 32 + pi];
                const float2 cs1 = g_ropecs[(s + 8) * 32 + pi];
                float e0 = v0.x * cs0.x - v0.y * cs0.y;
                float o0 = v0.y * cs0.x + v0.x * cs0.y;
                v0 = make_float2(e0, o0);
                float e1 = v1.x * cs1.x - v1.y * cs1.y;
                float o1 = v1.y * cs1.x + v1.x * cs1.y;
                v1 = make_float2(e1, o1);
            }
            if (SCATTER) {
                const int bb = row >> 11;
                const int h = col >> 6, dk = col & 63;
                float* dst = Out + (((size_t)bb * HH + h) * SS + s) * DKK + dk;
                *(float2*)dst = v0;
                *(float2*)(dst + 8 * DKK) = v1;
            } else {
                *(float2*)&Out[(size_t)row * DD + col] = v0;
                *(float2*)&Out[(size_t)(row + 8) * DD + col] = v1;
            }
        }
    }
}

__global__ __launch_bounds__(256, 2) void proj_qkv_kernel(
    const float* __restrict__ q, const float* __restrict__ k, const float* __restrict__ v,
    const float* __restrict__ bq, const float* __restrict__ bk,
    const float* __restrict__ bv)
{
    const float* A; const uint32_t* Wtf; const float* bias; float* Out;
    if (blockIdx.z == 0)      { A = q; Wtf = g_Wtf[0]; bias = bq; Out = g_Q; }
    else if (blockIdx.z == 1) { A = k; Wtf = g_Wtf[1]; bias = bk; Out = g_K; }
    else                      { A = v; Wtf = g_Wtf[2]; bias = bv; Out = g_V; }
    gemm_pipe_body<1>(A, Wtf, bias, Out, blockIdx.z < 2);
}

__global__ __launch_bounds__(256, 2) void proj_out_kernel(
    const float* __restrict__ bo, float* __restrict__ Out)
{
    gemm_pipe_body<0>(g_X, g_Wtf[3], bo, Out, false);
}

// ---------------------------------------------------------------------------
// Flash attention v2: 128 threads (4 warps), 32 query rows per warp
// (two m16 row-blocks processed sequentially), P via register shuffle
// (no smem round trip). smem = Q[128][68] + K[64][68] + V[64][72] = 69KB
// -> 3 CTAs/SM. Mask all-True.
// ---------------------------------------------------------------------------
#define FL_QS   0
#define FL_KS   (128*68)
#define FL_VS   (FL_KS + 64*68)
#define FL_U32  (FL_VS + 64*72)
#define FLASH_SMEM_BYTES (FL_U32 * sizeof(uint32_t))

__global__ __launch_bounds__(128) void flash_tc_kernel()
{
    extern __shared__ uint32_t smf[];
    uint32_t* Qs = smf + FL_QS;   // [128][68] tf32, pre-scaled
    uint32_t* Ks = smf + FL_KS;   // [64][68]
    uint32_t* Vs = smf + FL_VS;   // [64][72]

    const int bq0 = blockIdx.x * 128;
    const int hh = blockIdx.y, b = blockIdx.z;
    const int tid = threadIdx.x, lane = tid & 31, wid = tid >> 5;
    const int g = lane >> 2, t4 = lane & 3;

    const size_t head_base = (((size_t)b * HH + hh) * SS) * DKK;
    const float* Qg = g_Q + head_base + (size_t)bq0 * DKK;

    // Load Q tile (pre-scaled by 1/sqrt(64), tf32): 2048 float4 / 128 thr
#pragma unroll
    for (int it = 0; it < 16; it++) {
        const int idx = tid + it * 128;
        const int row = idx >> 4, c4 = (idx & 15) * 4;
        float4 qv = *(const float4*)(Qg + (size_t)row * DKK + c4);
        uint4 u;
        u.x = f2tf(qv.x * 0.125f); u.y = f2tf(qv.y * 0.125f);
        u.z = f2tf(qv.z * 0.125f); u.w = f2tf(qv.w * 0.125f);
        *(uint4*)&Qs[row * 68 + c4] = u;
    }

    // Accumulators: 2 row-blocks x 8 dk-groups x 4
    float of[2][8][4];
#pragma unroll
    for (int h = 0; h < 2; h++)
#pragma unroll
        for (int ni = 0; ni < 8; ni++)
#pragma unroll
            for (int r = 0; r < 4; r++) of[h][ni][r] = 0.f;
    float mrow[2][2], lrow[2][2];
#pragma unroll
    for (int h = 0; h < 2; h++) {
        mrow[h][0] = -INFINITY; mrow[h][1] = -INFINITY;
        lrow[h][0] = 0.f;       lrow[h][1] = 0.f;
    }

    for (int kt = 0; kt < SS / 64; kt++) {
        const float* Kg = g_K + head_base + (size_t)(kt * 64) * DKK;
        const float* Vg = g_V + head_base + (size_t)(kt * 64) * DKK;
        __syncthreads();   // prior tile's reads complete before overwrite
#pragma unroll
        for (int it = 0; it < 8; it++) {
            const int idx = tid + it * 128;
            const int row = idx >> 4, c4 = (idx & 15) * 4;
            float4 kv = *(const float4*)(Kg + (size_t)row * DKK + c4);
            uint4 ku;
            ku.x = f2tf(kv.x); ku.y = f2tf(kv.y); ku.z = f2tf(kv.z); ku.w = f2tf(kv.w);
            *(uint4*)&Ks[row * 68 + c4] = ku;
            float4 vv = *(const float4*)(Vg + (size_t)row * DKK + c4);
            uint4 vu;
            vu.x = f2tf(vv.x); vu.y = f2tf(vv.y); vu.z = f2tf(vv.z); vu.w = f2tf(vv.w);
            *(uint4*)&Vs[row * 72 + c4] = vu;
        }
        __syncthreads();

#pragma unroll
        for (int h = 0; h < 2; h++) {
            const int r0 = wid * 32 + h * 16;

            // S = Q K^T for rows [r0, r0+16)
            float sf[8][4];
#pragma unroll
            for (int ni = 0; ni < 8; ni++)
#pragma unroll
                for (int r = 0; r < 4; r++) sf[ni][r] = 0.f;
#pragma unroll
            for (int k8 = 0; k8 < 8; k8++) {
                const int kb = k8 * 8;
                uint32_t af[4];
                af[0] = Qs[(r0 + g) * 68 + kb + t4];
                af[1] = Qs[(r0 + g + 8) * 68 + kb + t4];
                af[2] = Qs[(r0 + g) * 68 + kb + t4 + 4];
                af[3] = Qs[(r0 + g + 8) * 68 + kb + t4 + 4];
#pragma unroll
                for (int ni = 0; ni < 8; ni++) {
                    const int key = ni * 8 + g;
                    uint32_t bf[2];
                    bf[0] = Ks[key * 68 + kb + t4];
                    bf[1] = Ks[key * 68 + kb + t4 + 4];
                    mma_tf32(sf[ni], af, bf);
                }
            }

            // Online softmax (rows r0+g / r0+g+8, reduce over t4 lanes)
            float mxA = -INFINITY, mxB = -INFINITY;
#pragma unroll
            for (int ni = 0; ni < 8; ni++) {
                mxA = fmaxf(mxA, fmaxf(sf[ni][0], sf[ni][1]));
                mxB = fmaxf(mxB, fmaxf(sf[ni][2], sf[ni][3]));
            }
            mxA = fmaxf(mxA, __shfl_xor_sync(0xffffffffu, mxA, 1));
            mxA = fmaxf(mxA, __shfl_xor_sync(0xffffffffu, mxA, 2));
            mxB = fmaxf(mxB, __shfl_xor_sync(0xffffffffu, mxB, 1));
            mxB = fmaxf(mxB, __shfl_xor_sync(0xffffffffu, mxB, 2));

            const float nmA = fmaxf(mrow[h][0], mxA), nmB = fmaxf(mrow[h][1], mxB);
            const float corrA = expf(mrow[h][0] - nmA), corrB = expf(mrow[h][1] - nmB);
            float sumA = 0.f, sumB = 0.f;
            // exp, accumulate row sums, convert P to tf32 bits in place
#pragma unroll
            for (int ni = 0; ni < 8; ni++) {
                const float p0 = expf(sf[ni][0] - nmA);
                const float p1 = expf(sf[ni][1] - nmA);
                const float p2 = expf(sf[ni][2] - nmB);
                const float p3 = expf(sf[ni][3] - nmB);
                sumA += p0 + p1;
                sumB += p2 + p3;
                sf[ni][0] = __uint_as_float(f2tf(p0));
                sf[ni][1] = __uint_as_float(f2tf(p1));
                sf[ni][2] = __uint_as_float(f2tf(p2));
                sf[ni][3] = __uint_as_float(f2tf(p3));
            }
            sumA += __shfl_xor_sync(0xffffffffu, sumA, 1);
            sumA += __shfl_xor_sync(0xffffffffu, sumA, 2);
            sumB += __shfl_xor_sync(0xffffffffu, sumB, 1);
            sumB += __shfl_xor_sync(0xffffffffu, sumB, 2);
            lrow[h][0] = lrow[h][0] * corrA + sumA;
            lrow[h][1] = lrow[h][1] * corrB + sumB;
            mrow[h][0] = nmA; mrow[h][1] = nmB;
#pragma unroll
            for (int ni = 0; ni < 8; ni++) {
                of[h][ni][0] *= corrA; of[h][ni][1] *= corrA;
                of[h][ni][2] *= corrB; of[h][ni][3] *= corrB;
            }

            // O += P V : A-frags of P built by shuffle from the C-frags (sf).
            // C-frag: lane(g,t4) holds P[r0+g][kb+2t4 +0/1] (sf0/1),
            //                        P[r0+g+8][kb+2t4 +0/1] (sf2/3).
            // A-frag needs: a0=P[g][kb+t4] a1=P[g+8][kb+t4]
            //               a2=P[g][kb+t4+4] a3=P[g+8][kb+t4+4]
            // col kb+c is held in component c&1 of lane 4g+(c>>1).
            const int src0 = 4 * g + (t4 >> 1);
            const int src1 = src0 + 2;
            const bool odd = (t4 & 1);
#pragma unroll
            for (int k8 = 0; k8 < 8; k8++) {
                const uint32_t u0 = __float_as_uint(sf[k8][0]);
                const uint32_t u1 = __float_as_uint(sf[k8][1]);
                const uint32_t u2 = __float_as_uint(sf[k8][2]);
                const uint32_t u3 = __float_as_uint(sf[k8][3]);
                const uint32_t x00 = __shfl_sync(0xffffffffu, u0, src0);
                const uint32_t x01 = __shfl_sync(0xffffffffu, u1, src0);
                const uint32_t x20 = __shfl_sync(0xffffffffu, u2, src0);
                const uint32_t x21 = __shfl_sync(0xffffffffu, u3, src0);
                const uint32_t y00 = __shfl_sync(0xffffffffu, u0, src1);
                const uint32_t y01 = __shfl_sync(0xffffffffu, u1, src1);
                const uint32_t y20 = __shfl_sync(0xffffffffu, u2, src1);
                const uint32_t y21 = __shfl_sync(0xffffffffu, u3, src1);
                uint32_t a[4];
                a[0] = odd ? x01 : x00;
                a[1] = odd ? x21 : x20;
                a[2] = odd ? y01 : y00;
                a[3] = odd ? y21 : y20;
                const int kb = k8 * 8;
#pragma unroll
                for (int ni = 0; ni < 8; ni++) {
                    const int dk = ni * 8 + g;
                    uint32_t bf[2];
                    bf[0] = Vs[(kb + t4) * 72 + dk];
                    bf[1] = Vs[(kb + t4 + 4) * 72 + dk];
                    mma_tf32(of[h][ni], a, bf);
                }
            }
        }
    }

    // Normalize, write to g_X [B,S,D]
#pragma unroll
    for (int h = 0; h < 2; h++) {
        const float invA = 1.f / lrow[h][0], invB = 1.f / lrow[h][1];
        const int rowA = bq0 + wid * 32 + h * 16 + g;
#pragma unroll
        for (int ni = 0; ni < 8; ni++) {
            const int dk = hh * DKK + ni * 8 + 2 * t4;
            float2 oA = make_float2(of[h][ni][0] * invA, of[h][ni][1] * invA);
            float2 oB = make_float2(of[h][ni][2] * invB, of[h][ni][3] * invB);
            *(float2*)&g_X[((size_t)b * SS + rowA) * DD + dk] = oA;
            *(float2*)&g_X[((size_t)b * SS + rowA + 8) * DD + dk] = oB;
        }
    }
}

// ---------------------------------------------------------------------------
extern "C" void kernel_launch(void* const* d_in, const int* in_sizes, int n_in,
                              void* d_out, int out_size)
{
    const float* q  = (const float*)d_in[0];
    const float* k  = (const float*)d_in[1];
    const float* v  = (const float*)d_in[2];
    // d_in[3] = mask: all-True in this problem, unused.
    const float* Wq = (const float*)d_in[4];
    const float* bq = (const float*)d_in[5];
    const float* Wk = (const float*)d_in[6];
    const float* bk = (const float*)d_in[7];
    const float* Wv = (const float*)d_in[8];
    const float* bv = (const float*)d_in[9];
    const float* Wo = (const float*)d_in[10];
    const float* bo = (const float*)d_in[11];
    float* out = (float*)d_out;

    // Pre-passes: RoPE table + tf32 weights
    rope_table_kernel<<<(SS * 32) / 256, 256>>>();
    cvt_w_kernel<<<dim3(DD * DD / 4 / 256, 4), 256>>>(Wq, Wk, Wv, Wo);

    // QKV projections (+fused RoPE on Q,K) -> [B,H,S,DK]
    cudaFuncSetAttribute(proj_qkv_kernel, cudaFuncAttributeMaxDynamicSharedMemorySize,
                         GT_SMEM_BYTES);
    cudaFuncSetAttribute(proj_out_kernel, cudaFuncAttributeMaxDynamicSharedMemorySize,
                         GT_SMEM_BYTES);
    proj_qkv_kernel<<<dim3(DD / 128, MROWS / 128, 3), 256, GT_SMEM_BYTES>>>(
        q, k, v, bq, bk, bv);

    // Flash attention (tf32 mma, 4 warps x 32 rows, P via shuffle)
    cudaFuncSetAttribute(flash_tc_kernel, cudaFuncAttributeMaxDynamicSharedMemorySize,
                         (int)FLASH_SMEM_BYTES);
    flash_tc_kernel<<<dim3(SS / 128, HH, BB), 128, FLASH_SMEM_BYTES>>>();

    // Output projection -> d_out
    proj_out_kernel<<<dim3(DD / 128, MROWS / 128), 256, GT_SMEM_BYTES>>>(bo, out);
}

// round 15
// speedup vs baseline: 1.0329x; 1.0329x over previous
#include <cuda_runtime.h>
#include <cuda_bf16.h>
#include <math.h>
#include <stdint.h>

// Problem constants
#define BB 4
#define SS 2048
#define DD 768
#define HH 12
#define DKK 64
#define MROWS (BB*SS)        // 8192

// Scratch (zero-init .bss; no runtime allocation)
__device__ uint32_t g_Q[BB*HH*SS*DKK]; // [B,H,S,DK] tf32 bits, pre-scaled 1/8
__device__ uint32_t g_K[BB*HH*SS*DKK]; // [B,H,S,DK] tf32 bits
__device__ uint32_t g_V[BB*HH*SS*DKK]; // [B,H,S,DK] tf32 bits
__device__ float g_X[BB*SS*DD];        // attention output, [B,S,D] fp32
__device__ uint32_t g_Wtf[4][DD*DD];   // weights pre-converted to tf32 bits
__device__ float2 g_ropecs[SS*32];     // (cos, sin) per (s, pair)

// ---------------------------------------------------------------------------
// Helpers
// ---------------------------------------------------------------------------
__device__ __forceinline__ uint32_t f2tf(float x) {
    uint32_t r;
    asm("cvt.rna.tf32.f32 %0, %1;" : "=r"(r) : "f"(x));
    return r;
}

__device__ __forceinline__ void mma_tf32(float* c, const uint32_t* a, const uint32_t* b) {
    asm volatile(
        "mma.sync.aligned.m16n8k8.row.col.f32.tf32.tf32.f32 "
        "{%0,%1,%2,%3}, {%4,%5,%6,%7}, {%8,%9}, {%0,%1,%2,%3};"
        : "+f"(c[0]), "+f"(c[1]), "+f"(c[2]), "+f"(c[3])
        : "r"(a[0]), "r"(a[1]), "r"(a[2]), "r"(a[3]), "r"(b[0]), "r"(b[1]));
}

__device__ __forceinline__ uint32_t smem_u32(const void* p) {
    uint32_t a;
    asm("{ .reg .u64 t; cvta.to.shared.u64 t, %1; cvt.u32.u64 %0, t; }"
        : "=r"(a) : "l"(p));
    return a;
}

__device__ __forceinline__ void cp16(uint32_t dst, const void* src) {
    asm volatile("cp.async.cg.shared.global [%0], [%1], 16;" :: "r"(dst), "l"(src));
}
#define CP_COMMIT() asm volatile("cp.async.commit_group;" ::: "memory")
#define CP_WAIT(N)  asm volatile("cp.async.wait_group %0;" :: "n"(N) : "memory")

// ---------------------------------------------------------------------------
// Pre-pass 1: RoPE cos/sin table. f32 angle (matches ref), double mod 2pi.
// ---------------------------------------------------------------------------
__global__ __launch_bounds__(256) void rope_table_kernel()
{
    const int t = blockIdx.x * blockDim.x + threadIdx.x;   // 2048*32
    const int i = t & 31, s = t >> 5;
    if (s >= SS) return;
    const float theta = powf(10000.f, (-2.f / 64.f) * (float)i);
    const float ang = (float)s * theta;
    const double TWO_PI = 6.283185307179586476925286766559;
    double ad = (double)ang;
    double r = ad - TWO_PI * floor(ad / TWO_PI);
    float rf = (float)r;
    g_ropecs[t] = make_float2(cosf(rf), sinf(rf));
}

// ---------------------------------------------------------------------------
// Pre-pass 2: convert 4 weight matrices to tf32 bits.
// ---------------------------------------------------------------------------
__global__ __launch_bounds__(256) void cvt_w_kernel(
    const float* __restrict__ Wq, const float* __restrict__ Wk,
    const float* __restrict__ Wv, const float* __restrict__ Wo)
{
    const float* W = (blockIdx.y == 0) ? Wq : (blockIdx.y == 1) ? Wk
                   : (blockIdx.y == 2) ? Wv : Wo;
    uint32_t* O = g_Wtf[blockIdx.y];
    const int i = (blockIdx.x * blockDim.x + threadIdx.x) * 4;
    float4 w = *(const float4*)(W + i);
    uint4 u;
    u.x = f2tf(w.x); u.y = f2tf(w.y); u.z = f2tf(w.z); u.w = f2tf(w.w);
    *(uint4*)(O + i) = u;
}

// ---------------------------------------------------------------------------
// cp.async-pipelined tf32 GEMM. SCATTER=1: write tf32 bits to [B,H,S,DK]
// (with optional RoPE and scale); SCATTER=0: write fp32 to [M,D].
// ---------------------------------------------------------------------------
#define ST_U32   8960                   // per stage: A 128*36 + B 32*136
#define GT_SMEM_BYTES (3 * ST_U32 * 4)  // 107520 B

template <int SCATTER>
__device__ __forceinline__ void gemm_pipe_body(
    const float* __restrict__ A, const uint32_t* __restrict__ Wtf,
    const float* __restrict__ bias, float* __restrict__ OutF,
    uint32_t* __restrict__ OutT, bool dorope, float oscale)
{
    extern __shared__ char smem[];
    const uint32_t sbase = smem_u32(smem);
    const int tid = threadIdx.x;
    const int lane = tid & 31, wid = tid >> 5;
    const int g = lane >> 2, t4 = lane & 3;
    const int wm = (wid & 1) * 64;
    const int wn = (wid >> 1) * 32;
    const int bm = blockIdx.y * 128, bn = blockIdx.x * 128;

    auto issue = [&](int ic, int st) {
        const int k0 = ic * 32;
        const uint32_t sb = sbase + st * (ST_U32 * 4);
#pragma unroll
        for (int it = 0; it < 4; it++) {
            const int seg = tid + it * 256;
            const int row = seg >> 3, c4 = (seg & 7) * 4;
            cp16(sb + (row * 36 + c4) * 4,
                 A + (size_t)(bm + row) * DD + k0 + c4);
        }
#pragma unroll
        for (int it = 0; it < 4; it++) {
            const int seg = tid + it * 256;
            const int row = seg >> 5, c4 = (seg & 31) * 4;
            cp16(sb + (4608 + row * 136 + c4) * 4,
                 Wtf + (size_t)(k0 + row) * DD + bn + c4);
        }
        CP_COMMIT();
    };

    float acc[4][4][4];
#pragma unroll
    for (int mi = 0; mi < 4; mi++)
#pragma unroll
        for (int ni = 0; ni < 4; ni++)
#pragma unroll
            for (int r = 0; r < 4; r++) acc[mi][ni][r] = 0.f;

    issue(0, 0);
    issue(1, 1);

    for (int ic = 0; ic < 24; ic++) {
        if (ic + 2 < 24) { issue(ic + 2, (ic + 2) % 3); CP_WAIT(2); }
        else if (ic + 1 < 24) { CP_WAIT(1); }
        else { CP_WAIT(0); }
        __syncthreads();

        const int st = ic % 3;
        const float* As = (const float*)smem + st * ST_U32;
        const uint32_t* Bs = (const uint32_t*)smem + st * ST_U32 + 4608;

#pragma unroll
        for (int k8 = 0; k8 < 4; k8++) {
            const int kb = k8 * 8;
            uint32_t af[4][4];
#pragma unroll
            for (int mi = 0; mi < 4; mi++) {
                const int r = wm + mi * 16 + g;
                af[mi][0] = f2tf(As[r * 36 + kb + t4]);
                af[mi][1] = f2tf(As[(r + 8) * 36 + kb + t4]);
                af[mi][2] = f2tf(As[r * 36 + kb + t4 + 4]);
                af[mi][3] = f2tf(As[(r + 8) * 36 + kb + t4 + 4]);
            }
            uint32_t bf[4][2];
#pragma unroll
            for (int ni = 0; ni < 4; ni++) {
                const int cn = wn + ni * 8 + g;
                bf[ni][0] = Bs[(kb + t4) * 136 + cn];
                bf[ni][1] = Bs[(kb + t4 + 4) * 136 + cn];
            }
#pragma unroll
            for (int mi = 0; mi < 4; mi++)
#pragma unroll
                for (int ni = 0; ni < 4; ni++)
                    mma_tf32(acc[mi][ni], af[mi], bf[ni]);
        }
        __syncthreads();
    }

#pragma unroll
    for (int mi = 0; mi < 4; mi++) {
#pragma unroll
        for (int ni = 0; ni < 4; ni++) {
            const int row = bm + wm + mi * 16 + g;
            const int col = bn + wn + ni * 8 + 2 * t4;
            const float b0 = bias[col], b1 = bias[col + 1];
            float2 v0 = make_float2(acc[mi][ni][0] + b0, acc[mi][ni][1] + b1);
            float2 v1 = make_float2(acc[mi][ni][2] + b0, acc[mi][ni][3] + b1);
            const int s = row & (SS - 1);
            if (dorope) {
                const int pi = (col & 63) >> 1;
                const float2 cs0 = g_ropecs[s * 32 + pi];
                const float2 cs1 = g_ropecs[(s + 8) * 32 + pi];
                float e0 = v0.x * cs0.x - v0.y * cs0.y;
                float o0 = v0.y * cs0.x + v0.x * cs0.y;
                v0 = make_float2(e0, o0);
                float e1 = v1.x * cs1.x - v1.y * cs1.y;
                float o1 = v1.y * cs1.x + v1.x * cs1.y;
                v1 = make_float2(e1, o1);
            }
            if (SCATTER) {
                const int bb = row >> 11;
                const int h = col >> 6, dk = col & 63;
                uint32_t* dst = OutT + (((size_t)bb * HH + h) * SS + s) * DKK + dk;
                uint2 u0, u1;
                u0.x = f2tf(v0.x * oscale); u0.y = f2tf(v0.y * oscale);
                u1.x = f2tf(v1.x * oscale); u1.y = f2tf(v1.y * oscale);
                *(uint2*)dst = u0;
                *(uint2*)(dst + 8 * DKK) = u1;
            } else {
                *(float2*)&OutF[(size_t)row * DD + col] = v0;
                *(float2*)&OutF[(size_t)(row + 8) * DD + col] = v1;
            }
        }
    }
}

__global__ __launch_bounds__(256, 2) void proj_qkv_kernel(
    const float* __restrict__ q, const float* __restrict__ k, const float* __restrict__ v,
    const float* __restrict__ bq, const float* __restrict__ bk,
    const float* __restrict__ bv)
{
    const float* A; const uint32_t* Wtf; const float* bias; uint32_t* Out; float sc;
    if (blockIdx.z == 0)      { A = q; Wtf = g_Wtf[0]; bias = bq; Out = g_Q; sc = 0.125f; }
    else if (blockIdx.z == 1) { A = k; Wtf = g_Wtf[1]; bias = bk; Out = g_K; sc = 1.f; }
    else                      { A = v; Wtf = g_Wtf[2]; bias = bv; Out = g_V; sc = 1.f; }
    gemm_pipe_body<1>(A, Wtf, bias, nullptr, Out, blockIdx.z < 2, sc);
}

__global__ __launch_bounds__(256, 2) void proj_out_kernel(
    const float* __restrict__ bo, float* __restrict__ Out)
{
    gemm_pipe_body<0>(g_X, g_Wtf[3], bo, Out, nullptr, false, 1.f);
}

// ---------------------------------------------------------------------------
// Flash attention v3: 256 threads (8 warps x 16 query rows), K-tile 32,
// double-buffered cp.async K/V staging (inputs already tf32 bits), P via
// per-warp smem. smem = Q[128][68] + 2*K[32][68] + 2*V[32][72] + P[128][36]
// = 22272 u32 = 87KB -> 2 CTAs/SM. Mask all-True.
// ---------------------------------------------------------------------------
#define FL_QS   0
#define FL_K0   (128*68)                 // 2 x 32*68 = 4352
#define FL_V0   (FL_K0 + 2*32*68)        // 2 x 32*72 = 4608
#define FL_PS   (FL_V0 + 2*32*72)        // 128*36 = 4608
#define FL_U32  (FL_PS + 128*36)
#define FLASH_SMEM_BYTES (FL_U32 * sizeof(uint32_t))
#define NKT (SS/32)                      // 64 tiles

__global__ __launch_bounds__(256, 2) void flash_tc_kernel()
{
    extern __shared__ uint32_t smf[];
    uint32_t* Qs = smf + FL_QS;
    uint32_t* Ps = smf + FL_PS;
    const uint32_t sb4 = smem_u32(smf);

    const int bq0 = blockIdx.x * 128;
    const int hh = blockIdx.y, b = blockIdx.z;
    const int tid = threadIdx.x, lane = tid & 31, wid = tid >> 5;
    const int g = lane >> 2, t4 = lane & 3;
    const int rw = wid * 16;

    const size_t head_base = (((size_t)b * HH + hh) * SS) * DKK;
    const uint32_t* Qg = g_Q + head_base + (size_t)bq0 * DKK;
    const uint32_t* Kg = g_K + head_base;
    const uint32_t* Vg = g_V + head_base;

    auto stageKV = [&](int kt, int buf) {
        const uint32_t kb = sb4 + (FL_K0 + buf * (32 * 68)) * 4;
        const uint32_t vb = sb4 + (FL_V0 + buf * (32 * 72)) * 4;
        const uint32_t* Kt = Kg + (size_t)kt * 32 * DKK;
        const uint32_t* Vt = Vg + (size_t)kt * 32 * DKK;
#pragma unroll
        for (int it = 0; it < 2; it++) {
            const int seg = tid + it * 256;        // 512 segs = 32 rows x 16
            const int row = seg >> 4, c4 = (seg & 15) * 4;
            cp16(kb + (row * 68 + c4) * 4, Kt + row * DKK + c4);
        }
#pragma unroll
        for (int it = 0; it < 2; it++) {
            const int seg = tid + it * 256;
            const int row = seg >> 4, c4 = (seg & 15) * 4;
            cp16(vb + (row * 72 + c4) * 4, Vt + row * DKK + c4);
        }
        CP_COMMIT();
    };

    // Stage Q tile (already tf32, pre-scaled)
#pragma unroll
    for (int it = 0; it < 8; it++) {
        const int idx = tid + it * 256;            // 2048 segs = 128 rows x 16
        const int row = idx >> 4, c4 = (idx & 15) * 4;
        *(uint4*)&Qs[row * 68 + c4] = *(const uint4*)(Qg + (size_t)row * DKK + c4);
    }

    float of[8][4];
#pragma unroll
    for (int ni = 0; ni < 8; ni++)
#pragma unroll
        for (int r = 0; r < 4; r++) of[ni][r] = 0.f;
    float mA = -INFINITY, mB = -INFINITY, lA = 0.f, lB = 0.f;

    stageKV(0, 0);

    for (int kt = 0; kt < NKT; kt++) {
        const int buf = kt & 1;
        CP_WAIT(0);
        __syncthreads();   // staged tile visible; all warps done with other buf
        if (kt + 1 < NKT) stageKV(kt + 1, buf ^ 1);

        const uint32_t* Ksb = smf + FL_K0 + buf * (32 * 68);
        const uint32_t* Vsb = smf + FL_V0 + buf * (32 * 72);

        // S = Q K^T : 16 rows x 32 keys
        float sf[4][4];
#pragma unroll
        for (int ni = 0; ni < 4; ni++)
#pragma unroll
            for (int r = 0; r < 4; r++) sf[ni][r] = 0.f;
#pragma unroll
        for (int k8 = 0; k8 < 8; k8++) {
            const int kb = k8 * 8;
            uint32_t af[4];
            af[0] = Qs[(rw + g) * 68 + kb + t4];
            af[1] = Qs[(rw + g + 8) * 68 + kb + t4];
            af[2] = Qs[(rw + g) * 68 + kb + t4 + 4];
            af[3] = Qs[(rw + g + 8) * 68 + kb + t4 + 4];
#pragma unroll
            for (int ni = 0; ni < 4; ni++) {
                const int key = ni * 8 + g;
                uint32_t bf[2];
                bf[0] = Ksb[key * 68 + kb + t4];
                bf[1] = Ksb[key * 68 + kb + t4 + 4];
                mma_tf32(sf[ni], af, bf);
            }
        }

        // Online softmax (rows rw+g / rw+g+8, reduce over t4 lanes)
        float mxA = -INFINITY, mxB = -INFINITY;
#pragma unroll
        for (int ni = 0; ni < 4; ni++) {
            mxA = fmaxf(mxA, fmaxf(sf[ni][0], sf[ni][1]));
            mxB = fmaxf(mxB, fmaxf(sf[ni][2], sf[ni][3]));
        }
        mxA = fmaxf(mxA, __shfl_xor_sync(0xffffffffu, mxA, 1));
        mxA = fmaxf(mxA, __shfl_xor_sync(0xffffffffu, mxA, 2));
        mxB = fmaxf(mxB, __shfl_xor_sync(0xffffffffu, mxB, 1));
        mxB = fmaxf(mxB, __shfl_xor_sync(0xffffffffu, mxB, 2));

        const float nmA = fmaxf(mA, mxA), nmB = fmaxf(mB, mxB);
        const float corrA = expf(mA - nmA), corrB = expf(mB - nmB);
        float sumA = 0.f, sumB = 0.f;
#pragma unroll
        for (int ni = 0; ni < 4; ni++) {
            const float p0 = expf(sf[ni][0] - nmA);
            const float p1 = expf(sf[ni][1] - nmA);
            sumA += p0 + p1;
            uint2 uA; uA.x = f2tf(p0); uA.y = f2tf(p1);
            *(uint2*)&Ps[(rw + g) * 36 + ni * 8 + 2 * t4] = uA;
            const float p2 = expf(sf[ni][2] - nmB);
            const float p3 = expf(sf[ni][3] - nmB);
            sumB += p2 + p3;
            uint2 uB; uB.x = f2tf(p2); uB.y = f2tf(p3);
            *(uint2*)&Ps[(rw + g + 8) * 36 + ni * 8 + 2 * t4] = uB;
        }
        sumA += __shfl_xor_sync(0xffffffffu, sumA, 1);
        sumA += __shfl_xor_sync(0xffffffffu, sumA, 2);
        sumB += __shfl_xor_sync(0xffffffffu, sumB, 1);
        sumB += __shfl_xor_sync(0xffffffffu, sumB, 2);
        lA = lA * corrA + sumA;
        lB = lB * corrB + sumB;
        mA = nmA; mB = nmB;
#pragma unroll
        for (int ni = 0; ni < 8; ni++) {
            of[ni][0] *= corrA; of[ni][1] *= corrA;
            of[ni][2] *= corrB; of[ni][3] *= corrB;
        }
        __syncwarp();   // P rows are warp-private

        // O += P V
#pragma unroll
        for (int k8 = 0; k8 < 4; k8++) {
            const int kb = k8 * 8;
            uint32_t af[4];
            af[0] = Ps[(rw + g) * 36 + kb + t4];
            af[1] = Ps[(rw + g + 8) * 36 + kb + t4];
            af[2] = Ps[(rw + g) * 36 + kb + t4 + 4];
            af[3] = Ps[(rw + g + 8) * 36 + kb + t4 + 4];
#pragma unroll
            for (int ni = 0; ni < 8; ni++) {
                const int dk = ni * 8 + g;
                uint32_t bf[2];
                bf[0] = Vsb[(kb + t4) * 72 + dk];
                bf[1] = Vsb[(kb + t4 + 4) * 72 + dk];
                mma_tf32(of[ni], af, bf);
            }
        }
        __syncwarp();   // P reads done before next tile overwrites
    }

    // Normalize, write to g_X [B,S,D]
    const float invA = 1.f / lA, invB = 1.f / lB;
    const int rowA = bq0 + rw + g;
#pragma unroll
    for (int ni = 0; ni < 8; ni++) {
        const int dk = hh * DKK + ni * 8 + 2 * t4;
        float2 oA = make_float2(of[ni][0] * invA, of[ni][1] * invA);
        float2 oB = make_float2(of[ni][2] * invB, of[ni][3] * invB);
        *(float2*)&g_X[((size_t)b * SS + rowA) * DD + dk] = oA;
        *(float2*)&g_X[((size_t)b * SS + rowA + 8) * DD + dk] = oB;
    }
}

// ---------------------------------------------------------------------------
extern "C" void kernel_launch(void* const* d_in, const int* in_sizes, int n_in,
                              void* d_out, int out_size)
{
    const float* q  = (const float*)d_in[0];
    const float* k  = (const float*)d_in[1];
    const float* v  = (const float*)d_in[2];
    // d_in[3] = mask: all-True in this problem, unused.
    const float* Wq = (const float*)d_in[4];
    const float* bq = (const float*)d_in[5];
    const float* Wk = (const float*)d_in[6];
    const float* bk = (const float*)d_in[7];
    const float* Wv = (const float*)d_in[8];
    const float* bv = (const float*)d_in[9];
    const float* Wo = (const float*)d_in[10];
    const float* bo = (const float*)d_in[11];
    float* out = (float*)d_out;

    // Pre-passes: RoPE table + tf32 weights
    rope_table_kernel<<<(SS * 32) / 256, 256>>>();
    cvt_w_kernel<<<dim3(DD * DD / 4 / 256, 4), 256>>>(Wq, Wk, Wv, Wo);

    // QKV projections (+fused RoPE on Q,K; outputs tf32 bits) -> [B,H,S,DK]
    cudaFuncSetAttribute(proj_qkv_kernel, cudaFuncAttributeMaxDynamicSharedMemorySize,
                         GT_SMEM_BYTES);
    cudaFuncSetAttribute(proj_out_kernel, cudaFuncAttributeMaxDynamicSharedMemorySize,
                         GT_SMEM_BYTES);
    proj_qkv_kernel<<<dim3(DD / 128, MROWS / 128, 3), 256, GT_SMEM_BYTES>>>(
        q, k, v, bq, bk, bv);

    // Flash attention (tf32 mma, 8 warps x 16 rows, cp.async double buffer)
    cudaFuncSetAttribute(flash_tc_kernel, cudaFuncAttributeMaxDynamicSharedMemorySize,
                         (int)FLASH_SMEM_BYTES);
    flash_tc_kernel<<<dim3(SS / 128, HH, BB), 256, FLASH_SMEM_BYTES>>>();

    // Output projection -> d_out
    proj_out_kernel<<<dim3(DD / 128, MROWS / 128), 256, GT_SMEM_BYTES>>>(bo, out);
}

// round 17
// speedup vs baseline: 1.1536x; 1.1169x over previous
#include <cuda_runtime.h>
#include <cuda_bf16.h>
#include <math.h>
#include <stdint.h>

// Problem constants
#define BB 4
#define SS 2048
#define DD 768
#define HH 12
#define DKK 64
#define MROWS (BB*SS)        // 8192

// Scratch (zero-init .bss; no runtime allocation)
__device__ uint32_t g_Q[BB*HH*SS*DKK]; // [B,H,S,DK] tf32 bits, pre-scaled 1/8
__device__ uint32_t g_K[BB*HH*SS*DKK]; // [B,H,S,DK] tf32 bits
__device__ uint32_t g_V[BB*HH*SS*DKK]; // [B,H,S,DK] tf32 bits
__device__ float g_X[BB*SS*DD];        // attention output, [B,S,D] fp32
__device__ uint32_t g_Wtf[4][DD*DD];   // weights pre-converted to tf32 bits
__device__ float2 g_ropecs[SS*32];     // (cos, sin) per (s, pair)

// ---------------------------------------------------------------------------
// Helpers
// ---------------------------------------------------------------------------
__device__ __forceinline__ uint32_t f2tf(float x) {
    uint32_t r;
    asm("cvt.rna.tf32.f32 %0, %1;" : "=r"(r) : "f"(x));
    return r;
}

__device__ __forceinline__ void mma_tf32(float* c, const uint32_t* a, const uint32_t* b) {
    asm volatile(
        "mma.sync.aligned.m16n8k8.row.col.f32.tf32.tf32.f32 "
        "{%0,%1,%2,%3}, {%4,%5,%6,%7}, {%8,%9}, {%0,%1,%2,%3};"
        : "+f"(c[0]), "+f"(c[1]), "+f"(c[2]), "+f"(c[3])
        : "r"(a[0]), "r"(a[1]), "r"(a[2]), "r"(a[3]), "r"(b[0]), "r"(b[1]));
}

__device__ __forceinline__ uint32_t smem_u32(const void* p) {
    uint32_t a;
    asm("{ .reg .u64 t; cvta.to.shared.u64 t, %1; cvt.u32.u64 %0, t; }"
        : "=r"(a) : "l"(p));
    return a;
}

__device__ __forceinline__ void cp16(uint32_t dst, const void* src) {
    asm volatile("cp.async.cg.shared.global [%0], [%1], 16;" :: "r"(dst), "l"(src));
}
#define CP_COMMIT() asm volatile("cp.async.commit_group;" ::: "memory")
#define CP_WAIT(N)  asm volatile("cp.async.wait_group %0;" :: "n"(N) : "memory")

// ---------------------------------------------------------------------------
// Pre-pass 1: RoPE cos/sin table. f32 angle (matches ref), double mod 2pi.
// ---------------------------------------------------------------------------
__global__ __launch_bounds__(256) void rope_table_kernel()
{
    const int t = blockIdx.x * blockDim.x + threadIdx.x;   // 2048*32
    const int i = t & 31, s = t >> 5;
    if (s >= SS) return;
    const float theta = powf(10000.f, (-2.f / 64.f) * (float)i);
    const float ang = (float)s * theta;
    const double TWO_PI = 6.283185307179586476925286766559;
    double ad = (double)ang;
    double r = ad - TWO_PI * floor(ad / TWO_PI);
    float rf = (float)r;
    g_ropecs[t] = make_float2(cosf(rf), sinf(rf));
}

// ---------------------------------------------------------------------------
// Pre-pass 2: convert 4 weight matrices to tf32 bits.
// ---------------------------------------------------------------------------
__global__ __launch_bounds__(256) void cvt_w_kernel(
    const float* __restrict__ Wq, const float* __restrict__ Wk,
    const float* __restrict__ Wv, const float* __restrict__ Wo)
{
    const float* W = (blockIdx.y == 0) ? Wq : (blockIdx.y == 1) ? Wk
                   : (blockIdx.y == 2) ? Wv : Wo;
    uint32_t* O = g_Wtf[blockIdx.y];
    const int i = (blockIdx.x * blockDim.x + threadIdx.x) * 4;
    float4 w = *(const float4*)(W + i);
    uint4 u;
    u.x = f2tf(w.x); u.y = f2tf(w.y); u.z = f2tf(w.z); u.w = f2tf(w.w);
    *(uint4*)(O + i) = u;
}

// ---------------------------------------------------------------------------
// cp.async-pipelined tf32 GEMM (unchanged from R15, passing).
// ---------------------------------------------------------------------------
#define ST_U32   8960                   // per stage: A 128*36 + B 32*136
#define GT_SMEM_BYTES (3 * ST_U32 * 4)  // 107520 B

template <int SCATTER>
__device__ __forceinline__ void gemm_pipe_body(
    const float* __restrict__ A, const uint32_t* __restrict__ Wtf,
    const float* __restrict__ bias, float* __restrict__ OutF,
    uint32_t* __restrict__ OutT, bool dorope, float oscale)
{
    extern __shared__ char smem[];
    const uint32_t sbase = smem_u32(smem);
    const int tid = threadIdx.x;
    const int lane = tid & 31, wid = tid >> 5;
    const int g = lane >> 2, t4 = lane & 3;
    const int wm = (wid & 1) * 64;
    const int wn = (wid >> 1) * 32;
    const int bm = blockIdx.y * 128, bn = blockIdx.x * 128;

    auto issue = [&](int ic, int st) {
        const int k0 = ic * 32;
        const uint32_t sb = sbase + st * (ST_U32 * 4);
#pragma unroll
        for (int it = 0; it < 4; it++) {
            const int seg = tid + it * 256;
            const int row = seg >> 3, c4 = (seg & 7) * 4;
            cp16(sb + (row * 36 + c4) * 4,
                 A + (size_t)(bm + row) * DD + k0 + c4);
        }
#pragma unroll
        for (int it = 0; it < 4; it++) {
            const int seg = tid + it * 256;
            const int row = seg >> 5, c4 = (seg & 31) * 4;
            cp16(sb + (4608 + row * 136 + c4) * 4,
                 Wtf + (size_t)(k0 + row) * DD + bn + c4);
        }
        CP_COMMIT();
    };

    float acc[4][4][4];
#pragma unroll
    for (int mi = 0; mi < 4; mi++)
#pragma unroll
        for (int ni = 0; ni < 4; ni++)
#pragma unroll
            for (int r = 0; r < 4; r++) acc[mi][ni][r] = 0.f;

    issue(0, 0);
    issue(1, 1);

    for (int ic = 0; ic < 24; ic++) {
        if (ic + 2 < 24) { issue(ic + 2, (ic + 2) % 3); CP_WAIT(2); }
        else if (ic + 1 < 24) { CP_WAIT(1); }
        else { CP_WAIT(0); }
        __syncthreads();

        const int st = ic % 3;
        const float* As = (const float*)smem + st * ST_U32;
        const uint32_t* Bs = (const uint32_t*)smem + st * ST_U32 + 4608;

#pragma unroll
        for (int k8 = 0; k8 < 4; k8++) {
            const int kb = k8 * 8;
            uint32_t af[4][4];
#pragma unroll
            for (int mi = 0; mi < 4; mi++) {
                const int r = wm + mi * 16 + g;
                af[mi][0] = f2tf(As[r * 36 + kb + t4]);
                af[mi][1] = f2tf(As[(r + 8) * 36 + kb + t4]);
                af[mi][2] = f2tf(As[r * 36 + kb + t4 + 4]);
                af[mi][3] = f2tf(As[(r + 8) * 36 + kb + t4 + 4]);
            }
            uint32_t bf[4][2];
#pragma unroll
            for (int ni = 0; ni < 4; ni++) {
                const int cn = wn + ni * 8 + g;
                bf[ni][0] = Bs[(kb + t4) * 136 + cn];
                bf[ni][1] = Bs[(kb + t4 + 4) * 136 + cn];
            }
#pragma unroll
            for (int mi = 0; mi < 4; mi++)
#pragma unroll
                for (int ni = 0; ni < 4; ni++)
                    mma_tf32(acc[mi][ni], af[mi], bf[ni]);
        }
        __syncthreads();
    }

#pragma unroll
    for (int mi = 0; mi < 4; mi++) {
#pragma unroll
        for (int ni = 0; ni < 4; ni++) {
            const int row = bm + wm + mi * 16 + g;
            const int col = bn + wn + ni * 8 + 2 * t4;
            const float b0 = bias[col], b1 = bias[col + 1];
            float2 v0 = make_float2(acc[mi][ni][0] + b0, acc[mi][ni][1] + b1);
            float2 v1 = make_float2(acc[mi][ni][2] + b0, acc[mi][ni][3] + b1);
            const int s = row & (SS - 1);
            if (dorope) {
                const int pi = (col & 63) >> 1;
                const float2 cs0 = g_ropecs[s * 32 + pi];
                const float2 cs1 = g_ropecs[(s + 8) * 32 + pi];
                float e0 = v0.x * cs0.x - v0.y * cs0.y;
                float o0 = v0.y * cs0.x + v0.x * cs0.y;
                v0 = make_float2(e0, o0);
                float e1 = v1.x * cs1.x - v1.y * cs1.y;
                float o1 = v1.y * cs1.x + v1.x * cs1.y;
                v1 = make_float2(e1, o1);
            }
            if (SCATTER) {
                const int bb = row >> 11;
                const int h = col >> 6, dk = col & 63;
                uint32_t* dst = OutT + (((size_t)bb * HH + h) * SS + s) * DKK + dk;
                uint2 u0, u1;
                u0.x = f2tf(v0.x * oscale); u0.y = f2tf(v0.y * oscale);
                u1.x = f2tf(v1.x * oscale); u1.y = f2tf(v1.y * oscale);
                *(uint2*)dst = u0;
                *(uint2*)(dst + 8 * DKK) = u1;
            } else {
                *(float2*)&OutF[(size_t)row * DD + col] = v0;
                *(float2*)&OutF[(size_t)(row + 8) * DD + col] = v1;
            }
        }
    }
}

__global__ __launch_bounds__(256, 2) void proj_qkv_kernel(
    const float* __restrict__ q, const float* __restrict__ k, const float* __restrict__ v,
    const float* __restrict__ bq, const float* __restrict__ bk,
    const float* __restrict__ bv)
{
    const float* A; const uint32_t* Wtf; const float* bias; uint32_t* Out; float sc;
    if (blockIdx.z == 0)      { A = q; Wtf = g_Wtf[0]; bias = bq; Out = g_Q; sc = 0.125f; }
    else if (blockIdx.z == 1) { A = k; Wtf = g_Wtf[1]; bias = bk; Out = g_K; sc = 1.f; }
    else                      { A = v; Wtf = g_Wtf[2]; bias = bv; Out = g_V; sc = 1.f; }
    gemm_pipe_body<1>(A, Wtf, bias, nullptr, Out, blockIdx.z < 2, sc);
}

__global__ __launch_bounds__(256, 2) void proj_out_kernel(
    const float* __restrict__ bo, float* __restrict__ Out)
{
    gemm_pipe_body<0>(g_X, g_Wtf[3], bo, Out, nullptr, false, 1.f);
}

// ---------------------------------------------------------------------------
// Flash attention v4: 128 threads (4 warps x 16 query rows = 64-query block),
// Q fragments in REGISTERS (loaded once), K-tile 32 double-buffered cp.async,
// P via per-warp smem. smem = 2*K[32][68] + 2*V[32][72] + P[64][36]
// = 11264 u32 = 44KB -> 4 CTAs/SM (regs capped 128 by launch_bounds).
// Mask all-True. Numerics identical to R15.
// ---------------------------------------------------------------------------
#define FL_K0   0                        // 2 x 32*68 = 4352
#define FL_V0   (2*32*68)                // 2 x 32*72 = 4608
#define FL_PS   (FL_V0 + 2*32*72)        // 64*36 = 2304
#define FL_U32  (FL_PS + 64*36)
#define FLASH_SMEM_BYTES (FL_U32 * sizeof(uint32_t))
#define NKT (SS/32)                      // 64 tiles

__global__ __launch_bounds__(128, 4) void flash_tc_kernel()
{
    extern __shared__ uint32_t smf[];
    uint32_t* Ps = smf + FL_PS;
    const uint32_t sb4 = smem_u32(smf);

    const int bq0 = blockIdx.x * 64;
    const int hh = blockIdx.y, b = blockIdx.z;
    const int tid = threadIdx.x, lane = tid & 31, wid = tid >> 5;
    const int g = lane >> 2, t4 = lane & 3;
    const int rw = wid * 16;

    const size_t head_base = (((size_t)b * HH + hh) * SS) * DKK;
    const uint32_t* Qg = g_Q + head_base + (size_t)bq0 * DKK;
    const uint32_t* Kg = g_K + head_base;
    const uint32_t* Vg = g_V + head_base;

    auto stageKV = [&](int kt, int buf) {
        const uint32_t kb = sb4 + (FL_K0 + buf * (32 * 68)) * 4;
        const uint32_t vb = sb4 + (FL_V0 + buf * (32 * 72)) * 4;
        const uint32_t* Kt = Kg + (size_t)kt * 32 * DKK;
        const uint32_t* Vt = Vg + (size_t)kt * 32 * DKK;
#pragma unroll
        for (int it = 0; it < 4; it++) {
            const int seg = tid + it * 128;        // 512 segs = 32 rows x 16
            const int row = seg >> 4, c4 = (seg & 15) * 4;
            cp16(kb + (row * 68 + c4) * 4, Kt + row * DKK + c4);
        }
#pragma unroll
        for (int it = 0; it < 4; it++) {
            const int seg = tid + it * 128;
            const int row = seg >> 4, c4 = (seg & 15) * 4;
            cp16(vb + (row * 72 + c4) * 4, Vt + row * DKK + c4);
        }
        CP_COMMIT();
    };

    stageKV(0, 0);

    // Q fragments -> registers (one-time; values identical to smem path)
    uint32_t qf[8][4];
#pragma unroll
    for (int k8 = 0; k8 < 8; k8++) {
        const int kb = k8 * 8;
        qf[k8][0] = Qg[(size_t)(rw + g) * DKK + kb + t4];
        qf[k8][1] = Qg[(size_t)(rw + g + 8) * DKK + kb + t4];
        qf[k8][2] = Qg[(size_t)(rw + g) * DKK + kb + t4 + 4];
        qf[k8][3] = Qg[(size_t)(rw + g + 8) * DKK + kb + t4 + 4];
    }

    float of[8][4];
#pragma unroll
    for (int ni = 0; ni < 8; ni++)
#pragma unroll
        for (int r = 0; r < 4; r++) of[ni][r] = 0.f;
    float mA = -INFINITY, mB = -INFINITY, lA = 0.f, lB = 0.f;

    for (int kt = 0; kt < NKT; kt++) {
        const int buf = kt & 1;
        CP_WAIT(0);
        __syncthreads();   // staged tile visible; all warps done with other buf
        if (kt + 1 < NKT) stageKV(kt + 1, buf ^ 1);

        const uint32_t* Ksb = smf + FL_K0 + buf * (32 * 68);
        const uint32_t* Vsb = smf + FL_V0 + buf * (32 * 72);

        // S = Q K^T : 16 rows x 32 keys (A-operand from registers)
        float sf[4][4];
#pragma unroll
        for (int ni = 0; ni < 4; ni++)
#pragma unroll
            for (int r = 0; r < 4; r++) sf[ni][r] = 0.f;
#pragma unroll
        for (int k8 = 0; k8 < 8; k8++) {
            const int kb = k8 * 8;
#pragma unroll
            for (int ni = 0; ni < 4; ni++) {
                const int key = ni * 8 + g;
                uint32_t bf[2];
                bf[0] = Ksb[key * 68 + kb + t4];
                bf[1] = Ksb[key * 68 + kb + t4 + 4];
                mma_tf32(sf[ni], qf[k8], bf);
            }
        }

        // Online softmax (rows rw+g / rw+g+8, reduce over t4 lanes)
        float mxA = -INFINITY, mxB = -INFINITY;
#pragma unroll
        for (int ni = 0; ni < 4; ni++) {
            mxA = fmaxf(mxA, fmaxf(sf[ni][0], sf[ni][1]));
            mxB = fmaxf(mxB, fmaxf(sf[ni][2], sf[ni][3]));
        }
        mxA = fmaxf(mxA, __shfl_xor_sync(0xffffffffu, mxA, 1));
        mxA = fmaxf(mxA, __shfl_xor_sync(0xffffffffu, mxA, 2));
        mxB = fmaxf(mxB, __shfl_xor_sync(0xffffffffu, mxB, 1));
        mxB = fmaxf(mxB, __shfl_xor_sync(0xffffffffu, mxB, 2));

        const float nmA = fmaxf(mA, mxA), nmB = fmaxf(mB, mxB);
        const float corrA = expf(mA - nmA), corrB = expf(mB - nmB);
        float sumA = 0.f, sumB = 0.f;
#pragma unroll
        for (int ni = 0; ni < 4; ni++) {
            const float p0 = expf(sf[ni][0] - nmA);
            const float p1 = expf(sf[ni][1] - nmA);
            sumA += p0 + p1;
            uint2 uA; uA.x = f2tf(p0); uA.y = f2tf(p1);
            *(uint2*)&Ps[(rw + g) * 36 + ni * 8 + 2 * t4] = uA;
            const float p2 = expf(sf[ni][2] - nmB);
            const float p3 = expf(sf[ni][3] - nmB);
            sumB += p2 + p3;
            uint2 uB; uB.x = f2tf(p2); uB.y = f2tf(p3);
            *(uint2*)&Ps[(rw + g + 8) * 36 + ni * 8 + 2 * t4] = uB;
        }
        sumA += __shfl_xor_sync(0xffffffffu, sumA, 1);
        sumA += __shfl_xor_sync(0xffffffffu, sumA, 2);
        sumB += __shfl_xor_sync(0xffffffffu, sumB, 1);
        sumB += __shfl_xor_sync(0xffffffffu, sumB, 2);
        lA = lA * corrA + sumA;
        lB = lB * corrB + sumB;
        mA = nmA; mB = nmB;
#pragma unroll
        for (int ni = 0; ni < 8; ni++) {
            of[ni][0] *= corrA; of[ni][1] *= corrA;
            of[ni][2] *= corrB; of[ni][3] *= corrB;
        }
        __syncwarp();   // P rows are warp-private

        // O += P V
#pragma unroll
        for (int k8 = 0; k8 < 4; k8++) {
            const int kb = k8 * 8;
            uint32_t af[4];
            af[0] = Ps[(rw + g) * 36 + kb + t4];
            af[1] = Ps[(rw + g + 8) * 36 + kb + t4];
            af[2] = Ps[(rw + g) * 36 + kb + t4 + 4];
            af[3] = Ps[(rw + g + 8) * 36 + kb + t4 + 4];
#pragma unroll
            for (int ni = 0; ni < 8; ni++) {
                const int dk = ni * 8 + g;
                uint32_t bf[2];
                bf[0] = Vsb[(kb + t4) * 72 + dk];
                bf[1] = Vsb[(kb + t4 + 4) * 72 + dk];
                mma_tf32(of[ni], af, bf);
            }
        }
        __syncwarp();   // P reads done before next tile overwrites
    }

    // Normalize, write to g_X [B,S,D]
    const float invA = 1.f / lA, invB = 1.f / lB;
    const int rowA = bq0 + rw + g;
#pragma unroll
    for (int ni = 0; ni < 8; ni++) {
        const int dk = hh * DKK + ni * 8 + 2 * t4;
        float2 oA = make_float2(of[ni][0] * invA, of[ni][1] * invA);
        float2 oB = make_float2(of[ni][2] * invB, of[ni][3] * invB);
        *(float2*)&g_X[((size_t)b * SS + rowA) * DD + dk] = oA;
        *(float2*)&g_X[((size_t)b * SS + rowA + 8) * DD + dk] = oB;
    }
}

// ---------------------------------------------------------------------------
extern "C" void kernel_launch(void* const* d_in, const int* in_sizes, int n_in,
                              void* d_out, int out_size)
{
    const float* q  = (const float*)d_in[0];
    const float* k  = (const float*)d_in[1];
    const float* v  = (const float*)d_in[2];
    // d_in[3] = mask: all-True in this problem, unused.
    const float* Wq = (const float*)d_in[4];
    const float* bq = (const float*)d_in[5];
    const float* Wk = (const float*)d_in[6];
    const float* bk = (const float*)d_in[7];
    const float* Wv = (const float*)d_in[8];
    const float* bv = (const float*)d_in[9];
    const float* Wo = (const float*)d_in[10];
    const float* bo = (const float*)d_in[11];
    float* out = (float*)d_out;

    // Pre-passes: RoPE table + tf32 weights
    rope_table_kernel<<<(SS * 32) / 256, 256>>>();
    cvt_w_kernel<<<dim3(DD * DD / 4 / 256, 4), 256>>>(Wq, Wk, Wv, Wo);

    // QKV projections (+fused RoPE on Q,K; outputs tf32 bits) -> [B,H,S,DK]
    cudaFuncSetAttribute(proj_qkv_kernel, cudaFuncAttributeMaxDynamicSharedMemorySize,
                         GT_SMEM_BYTES);
    cudaFuncSetAttribute(proj_out_kernel, cudaFuncAttributeMaxDynamicSharedMemorySize,
                         GT_SMEM_BYTES);
    proj_qkv_kernel<<<dim3(DD / 128, MROWS / 128, 3), 256, GT_SMEM_BYTES>>>(
        q, k, v, bq, bk, bv);

    // Flash attention (tf32 mma, 4 warps x 16 rows, Q in regs, 4 CTAs/SM)
    cudaFuncSetAttribute(flash_tc_kernel, cudaFuncAttributeMaxDynamicSharedMemorySize,
                         (int)FLASH_SMEM_BYTES);
    flash_tc_kernel<<<dim3(SS / 64, HH, BB), 128, FLASH_SMEM_BYTES>>>();

    // Output projection -> d_out
    proj_out_kernel<<<dim3(DD / 128, MROWS / 128), 256, GT_SMEM_BYTES>>>(bo, out);
}